// round 4
// baseline (speedup 1.0000x reference)
#include <cuda_runtime.h>
#include <cuda_bf16.h>
#include <cstdint>

// Problem constants
#define BB 4
#define SS 4096
#define DD 1024
#define MM (BB * SS)          // 16384
#define CH 64
#define LL (SS / CH)          // 64

// GEMM: Y[M, 3072] = A[M,1024] @ B[3072,1024]^T via int8 split
#define NTOT (3 * DD)         // 3072
#define CTA_M 128
#define CTA_N 128
#define KCH 64                // k elems per stage
#define NSTG (DD / KCH)       // 16 k-stages
#define ROWB 2048             // bytes per global row: 16 chunks * 128B (hi64|lo64)

#define SWZ(o) ((uint32_t)(o) ^ ((((uint32_t)(o)) >> 3) & 0x70))

#define NPIPE 3
#define STAGE_B 32768         // A 16KB + B 16KB
#define OFF_B 16384
#define SMEM_GEMM (NPIPE * STAGE_B)   // 96 KB

// quant scales
#define XMAX 7.0
#define WMAX 0.20
#define QMAXI 32639.0
static __device__ __forceinline__ float combine_scale() {
    return (float)((XMAX / QMAXI) * (WMAX / QMAXI));
}

// ---------------------------------------------------------------------------
// Device scratch
// ---------------------------------------------------------------------------
__device__ __align__(128) signed char g_Ai8[(size_t)MM * ROWB];
__device__ __align__(128) signed char g_Bi8[(size_t)NTOT * ROWB];
__device__ float g_bufG[(size_t)MM * DD];
__device__ float g_bufV[(size_t)MM * DD];
__device__ float g_bufA[(size_t)MM * DD];
__device__ float g_cA[BB * CH * DD];
__device__ float g_cH[BB * CH * DD];
__device__ float g_hin[BB * CH * DD];

// ---------------------------------------------------------------------------
// PTX helpers
// ---------------------------------------------------------------------------
__device__ __forceinline__ uint32_t smem_u32(const void* p) {
    uint32_t a;
    asm("{ .reg .u64 t; cvta.to.shared.u64 t, %1; cvt.u32.u64 %0, t; }" : "=r"(a) : "l"(p));
    return a;
}

#define CP_ASYNC16(sm, gp) \
    asm volatile("cp.async.cg.shared.global [%0], [%1], 16;" :: "r"(sm), "l"(gp))
#define CP_COMMIT() asm volatile("cp.async.commit_group;" ::: "memory")
#define CP_WAIT(N)  asm volatile("cp.async.wait_group %0;" :: "n"(N) : "memory")

#define LDSM_X4(r0, r1, r2, r3, addr) \
    asm volatile("ldmatrix.sync.aligned.m8n8.x4.shared.b16 {%0,%1,%2,%3}, [%4];" \
                 : "=r"(r0), "=r"(r1), "=r"(r2), "=r"(r3) : "r"(addr))

#define MMA_S8(c, a, b) \
    asm volatile("mma.sync.aligned.m16n8k32.row.col.s32.s8.s8.s32 " \
                 "{%0,%1,%2,%3}, {%4,%5,%6,%7}, {%8,%9}, {%0,%1,%2,%3};" \
                 : "+r"((c)[0]), "+r"((c)[1]), "+r"((c)[2]), "+r"((c)[3]) \
                 : "r"((a)[0]), "r"((a)[1]), "r"((a)[2]), "r"((a)[3]), \
                   "r"((b)[0]), "r"((b)[1]))

// ---------------------------------------------------------------------------
// Quantization: fp32 -> int16 -> (hi int8, lo int8), chunk-interleaved rows
// row layout: [chunk0: hi[0..63] | lo[0..63]][chunk1: ...] (128B per chunk)
// ---------------------------------------------------------------------------
__device__ __forceinline__ void q_split4(const float4 v, float qs,
                                         uchar4& hv, uchar4& lv)
{
    float f[4] = {v.x, v.y, v.z, v.w};
    unsigned char h[4], l[4];
#pragma unroll
    for (int q = 0; q < 4; ++q) {
        float c = fminf(fmaxf(f[q] * qs, -32639.0f), 32639.0f);
        int vi = __float2int_rn(c);
        int lo = (int)(signed char)(vi & 0xFF);
        int hi = (vi - lo) >> 8;
        h[q] = (unsigned char)(signed char)hi;
        l[q] = (unsigned char)(signed char)lo;
    }
    hv = make_uchar4(h[0], h[1], h[2], h[3]);
    lv = make_uchar4(l[0], l[1], l[2], l[3]);
}

__global__ __launch_bounds__(256)
void quantX_kernel(const float* __restrict__ x)
{
    int i = blockIdx.x * 256 + threadIdx.x;
    if (i >= MM * DD / 4) return;
    float4 v = reinterpret_cast<const float4*>(x)[i];
    int lin = i * 4;
    int m = lin >> 10;
    int k = lin & 1023;
    int c = k >> 6, pos = k & 63;
    uchar4 hv, lv;
    q_split4(v, (float)(QMAXI / XMAX), hv, lv);
    size_t base = (size_t)m * ROWB + c * 128 + pos;
    *reinterpret_cast<uchar4*>(g_Ai8 + base)      = hv;
    *reinterpret_cast<uchar4*>(g_Ai8 + base + 64) = lv;
}

__global__ __launch_bounds__(256)
void quantW_kernel(const float* __restrict__ w, int z)
{
    int i = blockIdx.x * 256 + threadIdx.x;
    if (i >= DD * DD / 4) return;
    float4 v = reinterpret_cast<const float4*>(w)[i];
    int lin = i * 4;
    int n = lin >> 10;
    int k = lin & 1023;
    int c = k >> 6, pos = k & 63;
    uchar4 hv, lv;
    q_split4(v, (float)(QMAXI / WMAX), hv, lv);
    size_t base = (size_t)(z * DD + n) * ROWB + c * 128 + pos;
    *reinterpret_cast<uchar4*>(g_Bi8 + base)      = hv;
    *reinterpret_cast<uchar4*>(g_Bi8 + base + 64) = lv;
}

// ---------------------------------------------------------------------------
// int8 IMMA GEMM + activation epilogue
// grid (NTOT/128 = 24, MM/128 = 128), 512 threads, 16 warps of 32x32
// ---------------------------------------------------------------------------
__global__ __launch_bounds__(512, 1)
void gemm_imma_kernel(const float* __restrict__ bg,
                      const float* __restrict__ bv,
                      const float* __restrict__ bd)
{
    extern __shared__ char smem[];
    const uint32_t smb = smem_u32(smem);

    const int tid  = threadIdx.x;
    const int wid  = tid >> 5;
    const int lane = tid & 31;
    const int wm = wid & 3;
    const int wn = wid >> 2;

    const int bn = blockIdx.x * CTA_N;
    const int bm = blockIdx.y * CTA_M;

    const signed char* Ab = g_Ai8 + (size_t)bm * ROWB;
    const signed char* Bb = g_Bi8 + (size_t)bn * ROWB;

    int accP0[2][4][4], accP1[2][4][4];
#pragma unroll
    for (int i = 0; i < 2; ++i)
#pragma unroll
        for (int j = 0; j < 4; ++j)
#pragma unroll
            for (int q = 0; q < 4; ++q) { accP0[i][j][q] = 0; accP1[i][j][q] = 0; }

    auto prefetch = [&](int c, int slot) {
        const uint32_t stA = smb + slot * STAGE_B;
        const uint32_t stB = stA + OFF_B;
#pragma unroll
        for (int it = 0; it < 2; ++it) {
            int u = tid + it * 512;
            int row = u >> 3, blk = u & 7;
            CP_ASYNC16(stA + SWZ(row * 128 + blk * 16),
                       Ab + (size_t)row * ROWB + c * 128 + blk * 16);
        }
#pragma unroll
        for (int it = 0; it < 2; ++it) {
            int u = tid + it * 512;
            int row = u >> 3, blk = u & 7;
            CP_ASYNC16(stB + SWZ(row * 128 + blk * 16),
                       Bb + (size_t)row * ROWB + c * 128 + blk * 16);
        }
        CP_COMMIT();
    };

    prefetch(0, 0);
    prefetch(1, 1);

    for (int c = 0; c < NSTG; ++c) {
        const int slot = c % NPIPE;
        CP_WAIT(1);
        __syncthreads();
        if (c + 2 < NSTG) prefetch(c + 2, (c + 2) % NPIPE);

        const uint32_t stA = smb + slot * STAGE_B;
        const uint32_t stB = stA + OFF_B;

#pragma unroll
        for (int ks = 0; ks < 2; ++ks) {
            uint32_t ah[2][4], al[2][4];
#pragma unroll
            for (int mi = 0; mi < 2; ++mi) {
                int rowA = wm * 32 + mi * 16 + (lane & 15);
                uint32_t base = rowA * 128 + ks * 32 + ((lane >> 4) << 4);
                LDSM_X4(ah[mi][0], ah[mi][1], ah[mi][2], ah[mi][3], stA + SWZ(base));
                LDSM_X4(al[mi][0], al[mi][1], al[mi][2], al[mi][3], stA + SWZ(base + 64));
            }
            uint32_t bh[4][2], bl[4][2];
#pragma unroll
            for (int p = 0; p < 2; ++p) {
                int nrow = wn * 32 + p * 16 + (lane & 7) + ((lane >> 4) << 3);
                uint32_t base = nrow * 128 + ks * 32 + (((lane >> 3) & 1) << 4);
                uint32_t r0, r1, r2, r3;
                LDSM_X4(r0, r1, r2, r3, stB + SWZ(base));
                bh[2 * p][0] = r0; bh[2 * p][1] = r1;
                bh[2 * p + 1][0] = r2; bh[2 * p + 1][1] = r3;
                LDSM_X4(r0, r1, r2, r3, stB + SWZ(base + 64));
                bl[2 * p][0] = r0; bl[2 * p][1] = r1;
                bl[2 * p + 1][0] = r2; bl[2 * p + 1][1] = r3;
            }
#pragma unroll
            for (int mi = 0; mi < 2; ++mi)
#pragma unroll
                for (int ni = 0; ni < 4; ++ni) {
                    MMA_S8(accP0[mi][ni], ah[mi], bh[ni]);
                    MMA_S8(accP1[mi][ni], ah[mi], bl[ni]);
                    MMA_S8(accP1[mi][ni], al[mi], bh[ni]);
                }
        }
    }

    // Epilogue
    const int z = blockIdx.x >> 3;                 // 8 CTAs of 128 cols per output
    const int nloc = bn & 1023;
    const float* bias = (z == 0) ? bg : (z == 1) ? bv : bd;
    float* outp = (z == 0) ? g_bufG : (z == 1) ? g_bufV : g_bufA;
    const float SCL = combine_scale();

#pragma unroll
    for (int mi = 0; mi < 2; ++mi) {
#pragma unroll
        for (int ni = 0; ni < 4; ++ni) {
            int row0 = bm + wm * 32 + mi * 16 + (lane >> 2);
            int col  = nloc + wn * 32 + ni * 8 + (lane & 3) * 2;
            float b0 = bias[col], b1 = bias[col + 1];
#pragma unroll
            for (int half = 0; half < 2; ++half) {
                int row = row0 + half * 8;
                float p0a = (float)accP0[mi][ni][half * 2 + 0];
                float p1a = (float)accP1[mi][ni][half * 2 + 0];
                float p0b = (float)accP0[mi][ni][half * 2 + 1];
                float p1b = (float)accP1[mi][ni][half * 2 + 1];
                float v0 = fmaf(65536.0f, p0a, 256.0f * p1a) * SCL + b0;
                float v1 = fmaf(65536.0f, p0b, 256.0f * p1b) * SCL + b1;
                float r0, r1;
                if (z == 0) {
                    r0 = 1.0f / (1.0f + __expf(-v0));
                    r1 = 1.0f / (1.0f + __expf(-v1));
                } else if (z == 1) {
                    r0 = tanhf(v0);
                    r1 = tanhf(v1);
                } else {
                    r0 = 0.001f + 0.998f / (1.0f + __expf(-v0));
                    r1 = 0.001f + 0.998f / (1.0f + __expf(-v1));
                }
                float2 o2; o2.x = r0; o2.y = r1;
                *reinterpret_cast<float2*>(outp + (size_t)row * DD + col) = o2;
            }
        }
    }
}

// ---------------------------------------------------------------------------
// Scan passes
// ---------------------------------------------------------------------------
__global__ __launch_bounds__(256)
void scan_pass1_kernel()
{
    const int d = blockIdx.x * 256 + threadIdx.x;
    const int c = blockIdx.y;
    const int b = blockIdx.z;

    size_t base = ((size_t)(b * SS + c * LL)) * DD + d;
    float A = 1.0f;
    float h = 0.0f;
#pragma unroll 4
    for (int s = 0; s < LL; ++s) {
        float a  = g_bufA[base];
        float xg = g_bufG[base];
        float xv = g_bufV[base];
        A *= a;
        h = fmaf(a, h, xg * xv);
        base += DD;
    }
    const size_t ci = (size_t)(b * CH + c) * DD + d;
    g_cA[ci] = A;
    g_cH[ci] = h;
}

__global__ __launch_bounds__(256)
void scan_pass2_kernel()
{
    const int d = blockIdx.x * 256 + threadIdx.x;
    const int b = blockIdx.y;

    float h = 0.0f;
#pragma unroll 4
    for (int c = 0; c < CH; ++c) {
        const size_t ci = (size_t)(b * CH + c) * DD + d;
        g_hin[ci] = h;
        h = fmaf(g_cA[ci], h, g_cH[ci]);
    }
}

__global__ __launch_bounds__(256)
void scan_pass3_kernel(float* __restrict__ out)
{
    const int d = blockIdx.x * 256 + threadIdx.x;
    const int c = blockIdx.y;
    const int b = blockIdx.z;

    size_t base = ((size_t)(b * SS + c * LL)) * DD + d;
    float h = g_hin[(size_t)(b * CH + c) * DD + d];
#pragma unroll 4
    for (int s = 0; s < LL; ++s) {
        float a  = g_bufA[base];
        float xg = g_bufG[base];
        float xv = g_bufV[base];
        h = fmaf(a, h, xg * xv);
        out[base] = h;
        base += DD;
    }
}

// ---------------------------------------------------------------------------
// Launch
// ---------------------------------------------------------------------------
extern "C" void kernel_launch(void* const* d_in, const int* in_sizes, int n_in,
                              void* d_out, int out_size)
{
    const float* x  = (const float*)d_in[0];
    const float* Wg = (const float*)d_in[1];
    const float* bg = (const float*)d_in[2];
    const float* Wv = (const float*)d_in[3];
    const float* bv = (const float*)d_in[4];
    const float* Wd = (const float*)d_in[5];
    const float* bd = (const float*)d_in[6];
    float* out = (float*)d_out;

    static int smem_set = 0;
    if (!smem_set) {
        cudaFuncSetAttribute(gemm_imma_kernel,
                             cudaFuncAttributeMaxDynamicSharedMemorySize, SMEM_GEMM);
        smem_set = 1;
    }

    quantX_kernel<<<(MM * DD / 4 + 255) / 256, 256>>>(x);
    quantW_kernel<<<(DD * DD / 4 + 255) / 256, 256>>>(Wg, 0);
    quantW_kernel<<<(DD * DD / 4 + 255) / 256, 256>>>(Wv, 1);
    quantW_kernel<<<(DD * DD / 4 + 255) / 256, 256>>>(Wd, 2);

    gemm_imma_kernel<<<dim3(NTOT / CTA_N, MM / CTA_M), 512, SMEM_GEMM>>>(bg, bv, bd);

    dim3 p1(DD / 256, CH, BB);
    scan_pass1_kernel<<<p1, 256>>>();
    dim3 p2(DD / 256, BB);
    scan_pass2_kernel<<<p2, 256>>>();
    scan_pass3_kernel<<<p1, 256>>>(out);
}

// round 5
// speedup vs baseline: 2.7401x; 2.7401x over previous
#include <cuda_runtime.h>
#include <cuda_bf16.h>
#include <cstdint>

// Problem constants
#define BB 4
#define SS 4096
#define DD 1024
#define MM (BB * SS)          // 16384
#define CH 64
#define LL (SS / CH)          // 64

// GEMM config: Y[M, 3072] = Ae[M, 3072k] @ Be[3072n, 3072k]^T  (K' = 3*DD)
#define KTOT (3 * DD)         // 3072
#define NTOT (3 * DD)         // 3072 output cols (g | v | d)
#define CTA_M 128
#define CTA_N 128
#define KC2 64                // k per stage
#define NC (KTOT / KC2)       // 48 stages

#define SWZ(o) ((uint32_t)(o) ^ ((((uint32_t)(o)) >> 3) & 0x70))

#define NPIPE 3
#define STAGE_BYTES 32768     // A: 128*128B = 16KB, B: 128*128B = 16KB
#define OFF_B 16384
#define SMEM_GEMM (NPIPE * STAGE_BYTES)   // 96 KB -> 2 CTAs/SM

// ---------------------------------------------------------------------------
// Device scratch
// ---------------------------------------------------------------------------
__device__ __nv_bfloat16 g_Ae[(size_t)MM * KTOT];     // [xh | xh | xl]
__device__ __nv_bfloat16 g_Be[(size_t)NTOT * KTOT];   // per row: [wh | wl | wh]
__device__ float g_bufG[(size_t)MM * DD];
__device__ float g_bufV[(size_t)MM * DD];
__device__ float g_bufA[(size_t)MM * DD];
__device__ float g_cA[BB * CH * DD];
__device__ float g_cH[BB * CH * DD];
__device__ float g_hin[BB * CH * DD];

// ---------------------------------------------------------------------------
// PTX helpers
// ---------------------------------------------------------------------------
__device__ __forceinline__ uint32_t smem_u32(const void* p) {
    uint32_t a;
    asm("{ .reg .u64 t; cvta.to.shared.u64 t, %1; cvt.u32.u64 %0, t; }" : "=r"(a) : "l"(p));
    return a;
}

#define CP_ASYNC16(sm, gp) \
    asm volatile("cp.async.cg.shared.global [%0], [%1], 16;" :: "r"(sm), "l"(gp))
#define CP_COMMIT() asm volatile("cp.async.commit_group;" ::: "memory")
#define CP_WAIT(N)  asm volatile("cp.async.wait_group %0;" :: "n"(N) : "memory")

#define LDSM_X4(r0, r1, r2, r3, addr) \
    asm volatile("ldmatrix.sync.aligned.m8n8.x4.shared.b16 {%0,%1,%2,%3}, [%4];" \
                 : "=r"(r0), "=r"(r1), "=r"(r2), "=r"(r3) : "r"(addr))

#define MMA_BF16(c, a, b) \
    asm volatile("mma.sync.aligned.m16n8k16.row.col.f32.bf16.bf16.f32 " \
                 "{%0,%1,%2,%3}, {%4,%5,%6,%7}, {%8,%9}, {%0,%1,%2,%3};" \
                 : "+f"((c)[0]), "+f"((c)[1]), "+f"((c)[2]), "+f"((c)[3]) \
                 : "r"((a)[0]), "r"((a)[1]), "r"((a)[2]), "r"((a)[3]), \
                   "r"((b)[0]), "r"((b)[1]))

// ---------------------------------------------------------------------------
// Split kernels: fp32 -> bf16 hi/lo into concatenated-K layouts
// ---------------------------------------------------------------------------
__global__ __launch_bounds__(256)
void splitX_kernel(const float* __restrict__ x)
{
    int i = blockIdx.x * 256 + threadIdx.x;            // float4 index
    if (i >= MM * DD / 4) return;
    float4 v = reinterpret_cast<const float4*>(x)[i];
    int lin = i * 4;
    int m = lin >> 10;           // /DD
    int k = lin & 1023;
    float f[4] = {v.x, v.y, v.z, v.w};
    unsigned short h[4], l[4];
#pragma unroll
    for (int q = 0; q < 4; ++q) {
        __nv_bfloat16 hb = __float2bfloat16(f[q]);
        __nv_bfloat16 lb = __float2bfloat16(f[q] - __bfloat162float(hb));
        h[q] = __bfloat16_as_ushort(hb);
        l[q] = __bfloat16_as_ushort(lb);
    }
    ushort4 hv = make_ushort4(h[0], h[1], h[2], h[3]);
    ushort4 lv = make_ushort4(l[0], l[1], l[2], l[3]);
    size_t base = (size_t)m * KTOT + k;
    *reinterpret_cast<ushort4*>(g_Ae + base)            = hv;   // xh
    *reinterpret_cast<ushort4*>(g_Ae + base + DD)       = hv;   // xh
    *reinterpret_cast<ushort4*>(g_Ae + base + 2 * DD)   = lv;   // xl
}

__global__ __launch_bounds__(256)
void splitW_kernel(const float* __restrict__ w, int z)
{
    int i = blockIdx.x * 256 + threadIdx.x;
    if (i >= DD * DD / 4) return;
    float4 v = reinterpret_cast<const float4*>(w)[i];
    int lin = i * 4;
    int n = lin >> 10;
    int k = lin & 1023;
    float f[4] = {v.x, v.y, v.z, v.w};
    unsigned short h[4], l[4];
#pragma unroll
    for (int q = 0; q < 4; ++q) {
        __nv_bfloat16 hb = __float2bfloat16(f[q]);
        __nv_bfloat16 lb = __float2bfloat16(f[q] - __bfloat162float(hb));
        h[q] = __bfloat16_as_ushort(hb);
        l[q] = __bfloat16_as_ushort(lb);
    }
    ushort4 hv = make_ushort4(h[0], h[1], h[2], h[3]);
    ushort4 lv = make_ushort4(l[0], l[1], l[2], l[3]);
    size_t base = (size_t)(z * DD + n) * KTOT + k;
    *reinterpret_cast<ushort4*>(g_Be + base)          = hv;   // wh
    *reinterpret_cast<ushort4*>(g_Be + base + DD)     = lv;   // wl
    *reinterpret_cast<ushort4*>(g_Be + base + 2 * DD) = hv;   // wh
}

// ---------------------------------------------------------------------------
// bf16 HMMA GEMM + activation epilogue
// grid (NTOT/CTA_N = 24, MM/CTA_M = 128), 256 threads, 8 warps of 32x64
// 3-stage cp.async pipeline, 1 barrier per stage, 2 CTAs/SM
// ---------------------------------------------------------------------------
__global__ __launch_bounds__(256, 2)
void gemm_hmma_kernel(const float* __restrict__ bg,
                      const float* __restrict__ bv,
                      const float* __restrict__ bd)
{
    extern __shared__ char smem[];
    const uint32_t smb = smem_u32(smem);

    const int tid  = threadIdx.x;
    const int wid  = tid >> 5;
    const int lane = tid & 31;
    const int wm = wid & 3;          // m-tile of 32 (4 tiles)
    const int wn = wid >> 2;         // n-tile of 64 (2 tiles)

    const int bn = blockIdx.x * CTA_N;
    const int bm = blockIdx.y * CTA_M;

    const __nv_bfloat16* Ab = g_Ae + (size_t)bm * KTOT;
    const __nv_bfloat16* Bb = g_Be + (size_t)bn * KTOT;

    float acc[2][8][4];
#pragma unroll
    for (int i = 0; i < 2; ++i)
#pragma unroll
        for (int j = 0; j < 8; ++j)
#pragma unroll
            for (int q = 0; q < 4; ++q) acc[i][j][q] = 0.0f;

    // prefetch stage c into pipeline slot
    auto prefetch = [&](int c, int slot) {
        const uint32_t stA = smb + slot * STAGE_BYTES;
        const uint32_t stB = stA + OFF_B;
        const size_t kb = (size_t)c * KC2;
        // A: 128 rows x 8 chunks of 16B = 1024 chunks; 256 threads -> 4 iters
#pragma unroll
        for (int it = 0; it < 4; ++it) {
            int u = tid + it * 256;
            int row = u >> 3, cc = u & 7;
            const char* gp = reinterpret_cast<const char*>(Ab + (size_t)row * KTOT + kb) + cc * 16;
            CP_ASYNC16(stA + SWZ(row * 128 + cc * 16), gp);
        }
        // B: 128 rows x 8 chunks
#pragma unroll
        for (int it = 0; it < 4; ++it) {
            int u = tid + it * 256;
            int row = u >> 3, cc = u & 7;
            const char* gp = reinterpret_cast<const char*>(Bb + (size_t)row * KTOT + kb) + cc * 16;
            CP_ASYNC16(stB + SWZ(row * 128 + cc * 16), gp);
        }
        CP_COMMIT();
    };

    prefetch(0, 0);
    prefetch(1, 1);

    for (int c = 0; c < NC; ++c) {
        const int slot = c % NPIPE;
        if (c == NC - 1) { CP_WAIT(0); } else { CP_WAIT(1); }
        __syncthreads();                      // stage c visible; slot (c+2)%3 free
        if (c + 2 < NC) prefetch(c + 2, (c + 2) % NPIPE);

        const uint32_t stA = smb + slot * STAGE_BYTES;
        const uint32_t stB = stA + OFF_B;

#pragma unroll
        for (int ks = 0; ks < KC2 / 16; ++ks) {
            uint32_t af[2][4];
#pragma unroll
            for (int mi = 0; mi < 2; ++mi) {
                int rowA = wm * 32 + mi * 16 + (lane & 15);
                uint32_t addr = stA + SWZ(rowA * 128 + ks * 32 + (lane >> 4) * 16);
                LDSM_X4(af[mi][0], af[mi][1], af[mi][2], af[mi][3], addr);
            }
            uint32_t bf[8][2];
#pragma unroll
            for (int p = 0; p < 4; ++p) {
                int nrow = wn * 64 + p * 16 + (lane & 7) + ((lane >> 4) << 3);
                uint32_t addr = stB + SWZ(nrow * 128 + ks * 32 + ((lane >> 3) & 1) * 16);
                uint32_t r0, r1, r2, r3;
                LDSM_X4(r0, r1, r2, r3, addr);
                bf[2 * p][0] = r0; bf[2 * p][1] = r1;
                bf[2 * p + 1][0] = r2; bf[2 * p + 1][1] = r3;
            }
#pragma unroll
            for (int mi = 0; mi < 2; ++mi)
#pragma unroll
                for (int ni = 0; ni < 8; ++ni)
                    MMA_BF16(acc[mi][ni], af[mi], bf[ni]);
        }
    }

    // Epilogue: bias + activation, write fp32
    const int z = blockIdx.x >> 3;          // 24 CTAs in x: 8 per output
    const int nloc = bn & 1023;
    const float* bias = (z == 0) ? bg : (z == 1) ? bv : bd;
    float* outp = (z == 0) ? g_bufG : (z == 1) ? g_bufV : g_bufA;

#pragma unroll
    for (int mi = 0; mi < 2; ++mi) {
#pragma unroll
        for (int ni = 0; ni < 8; ++ni) {
            int row0 = bm + wm * 32 + mi * 16 + (lane >> 2);
            int col  = nloc + wn * 64 + ni * 8 + (lane & 3) * 2;
            float b0 = bias[col], b1 = bias[col + 1];
#pragma unroll
            for (int half = 0; half < 2; ++half) {
                int row = row0 + half * 8;
                float v0 = acc[mi][ni][half * 2 + 0] + b0;
                float v1 = acc[mi][ni][half * 2 + 1] + b1;
                float r0, r1;
                if (z == 0) {
                    r0 = 1.0f / (1.0f + __expf(-v0));
                    r1 = 1.0f / (1.0f + __expf(-v1));
                } else if (z == 1) {
                    r0 = tanhf(v0);
                    r1 = tanhf(v1);
                } else {
                    r0 = 0.001f + 0.998f / (1.0f + __expf(-v0));
                    r1 = 0.001f + 0.998f / (1.0f + __expf(-v1));
                }
                float2 o2; o2.x = r0; o2.y = r1;
                *reinterpret_cast<float2*>(outp + (size_t)row * DD + col) = o2;
            }
        }
    }
}

// ---------------------------------------------------------------------------
// Scan passes
// ---------------------------------------------------------------------------
__global__ __launch_bounds__(256)
void scan_pass1_kernel()
{
    const int d = blockIdx.x * 256 + threadIdx.x;
    const int c = blockIdx.y;
    const int b = blockIdx.z;

    size_t base = ((size_t)(b * SS + c * LL)) * DD + d;
    float A = 1.0f;
    float h = 0.0f;
#pragma unroll 4
    for (int s = 0; s < LL; ++s) {
        float a  = g_bufA[base];
        float xg = g_bufG[base];
        float xv = g_bufV[base];
        A *= a;
        h = fmaf(a, h, xg * xv);
        base += DD;
    }
    const size_t ci = (size_t)(b * CH + c) * DD + d;
    g_cA[ci] = A;
    g_cH[ci] = h;
}

__global__ __launch_bounds__(256)
void scan_pass2_kernel()
{
    const int d = blockIdx.x * 256 + threadIdx.x;
    const int b = blockIdx.y;

    float h = 0.0f;
#pragma unroll 4
    for (int c = 0; c < CH; ++c) {
        const size_t ci = (size_t)(b * CH + c) * DD + d;
        g_hin[ci] = h;
        h = fmaf(g_cA[ci], h, g_cH[ci]);
    }
}

__global__ __launch_bounds__(256)
void scan_pass3_kernel(float* __restrict__ out)
{
    const int d = blockIdx.x * 256 + threadIdx.x;
    const int c = blockIdx.y;
    const int b = blockIdx.z;

    size_t base = ((size_t)(b * SS + c * LL)) * DD + d;
    float h = g_hin[(size_t)(b * CH + c) * DD + d];
#pragma unroll 4
    for (int s = 0; s < LL; ++s) {
        float a  = g_bufA[base];
        float xg = g_bufG[base];
        float xv = g_bufV[base];
        h = fmaf(a, h, xg * xv);
        out[base] = h;
        base += DD;
    }
}

// ---------------------------------------------------------------------------
// Launch
// ---------------------------------------------------------------------------
extern "C" void kernel_launch(void* const* d_in, const int* in_sizes, int n_in,
                              void* d_out, int out_size)
{
    const float* x  = (const float*)d_in[0];
    const float* Wg = (const float*)d_in[1];
    const float* bg = (const float*)d_in[2];
    const float* Wv = (const float*)d_in[3];
    const float* bv = (const float*)d_in[4];
    const float* Wd = (const float*)d_in[5];
    const float* bd = (const float*)d_in[6];
    float* out = (float*)d_out;

    cudaFuncSetAttribute(gemm_hmma_kernel,
                         cudaFuncAttributeMaxDynamicSharedMemorySize, SMEM_GEMM);

    splitX_kernel<<<(MM * DD / 4 + 255) / 256, 256>>>(x);
    splitW_kernel<<<(DD * DD / 4 + 255) / 256, 256>>>(Wg, 0);
    splitW_kernel<<<(DD * DD / 4 + 255) / 256, 256>>>(Wv, 1);
    splitW_kernel<<<(DD * DD / 4 + 255) / 256, 256>>>(Wd, 2);

    gemm_hmma_kernel<<<dim3(NTOT / CTA_N, MM / CTA_M), 256, SMEM_GEMM>>>(bg, bv, bd);

    dim3 p1(DD / 256, CH, BB);
    scan_pass1_kernel<<<p1, 256>>>();
    dim3 p2(DD / 256, BB);
    scan_pass2_kernel<<<p2, 256>>>();
    scan_pass3_kernel<<<p1, 256>>>(out);
}

// round 6
// speedup vs baseline: 2.8966x; 1.0571x over previous
#include <cuda_runtime.h>
#include <cuda_bf16.h>
#include <cstdint>

// Problem constants
#define BB 4
#define SS 4096
#define DD 1024
#define MM (BB * SS)          // 16384
#define CH 64
#define LL (SS / CH)          // 64

// GEMM: Y[M, 3072] = X[M,1024] @ W[3072,1024]^T, split bf16 (hi/lo packed rows)
#define NTOT (3 * DD)         // 3072
#define CTA_M 128
#define CTA_N 128
#define KC 32                 // k elems per stage (one 128B packed chunk per row)
#define NSTG (DD / KC)        // 32 stages
#define ROWB 4096             // bytes per packed global row: 32 chunks * 128B

#define SWZ(o) ((uint32_t)(o) ^ ((((uint32_t)(o)) >> 3) & 0x70))

#define NPIPE 3
#define STAGE_BYTES 32768     // A 16KB + B 16KB
#define OFF_B 16384
#define SMEM_GEMM (NPIPE * STAGE_BYTES)   // 96 KB -> 2 CTAs/SM

// ---------------------------------------------------------------------------
// Device scratch
// ---------------------------------------------------------------------------
// packed rows: per k32 chunk, 128B = [hi: 32 bf16 | lo: 32 bf16]
__device__ __align__(128) unsigned char g_Ap[(size_t)MM * ROWB];
__device__ __align__(128) unsigned char g_Bp[(size_t)NTOT * ROWB];
__device__ float g_bufG[(size_t)MM * DD];
__device__ float g_bufV[(size_t)MM * DD];
__device__ float g_bufA[(size_t)MM * DD];
__device__ float g_cA[BB * CH * DD];
__device__ float g_cH[BB * CH * DD];
__device__ float g_hin[BB * CH * DD];

// ---------------------------------------------------------------------------
// PTX helpers
// ---------------------------------------------------------------------------
__device__ __forceinline__ uint32_t smem_u32(const void* p) {
    uint32_t a;
    asm("{ .reg .u64 t; cvta.to.shared.u64 t, %1; cvt.u32.u64 %0, t; }" : "=r"(a) : "l"(p));
    return a;
}

#define CP_ASYNC16(sm, gp) \
    asm volatile("cp.async.cg.shared.global [%0], [%1], 16;" :: "r"(sm), "l"(gp))
#define CP_COMMIT() asm volatile("cp.async.commit_group;" ::: "memory")
#define CP_WAIT(N)  asm volatile("cp.async.wait_group %0;" :: "n"(N) : "memory")

#define LDSM_X4(r0, r1, r2, r3, addr) \
    asm volatile("ldmatrix.sync.aligned.m8n8.x4.shared.b16 {%0,%1,%2,%3}, [%4];" \
                 : "=r"(r0), "=r"(r1), "=r"(r2), "=r"(r3) : "r"(addr))

#define MMA_BF16(c, a, b) \
    asm volatile("mma.sync.aligned.m16n8k16.row.col.f32.bf16.bf16.f32 " \
                 "{%0,%1,%2,%3}, {%4,%5,%6,%7}, {%8,%9}, {%0,%1,%2,%3};" \
                 : "+f"((c)[0]), "+f"((c)[1]), "+f"((c)[2]), "+f"((c)[3]) \
                 : "r"((a)[0]), "r"((a)[1]), "r"((a)[2]), "r"((a)[3]), \
                   "r"((b)[0]), "r"((b)[1]))

// ---------------------------------------------------------------------------
// Split kernels: fp32 -> bf16 hi/lo into packed-row layout
// ---------------------------------------------------------------------------
__device__ __forceinline__ void split4(const float4 v, ushort4& hv, ushort4& lv)
{
    float f[4] = {v.x, v.y, v.z, v.w};
    unsigned short h[4], l[4];
#pragma unroll
    for (int q = 0; q < 4; ++q) {
        __nv_bfloat16 hb = __float2bfloat16(f[q]);
        __nv_bfloat16 lb = __float2bfloat16(f[q] - __bfloat162float(hb));
        h[q] = __bfloat16_as_ushort(hb);
        l[q] = __bfloat16_as_ushort(lb);
    }
    hv = make_ushort4(h[0], h[1], h[2], h[3]);
    lv = make_ushort4(l[0], l[1], l[2], l[3]);
}

__global__ __launch_bounds__(256)
void splitX_kernel(const float* __restrict__ x)
{
    int i = blockIdx.x * 256 + threadIdx.x;            // float4 index
    if (i >= MM * DD / 4) return;
    float4 v = reinterpret_cast<const float4*>(x)[i];
    int lin = i * 4;
    int m = lin >> 10;
    int k = lin & 1023;
    int chunk = k >> 5, pos = k & 31;
    ushort4 hv, lv;
    split4(v, hv, lv);
    size_t base = (size_t)m * ROWB + chunk * 128 + pos * 2;
    *reinterpret_cast<ushort4*>(g_Ap + base)      = hv;
    *reinterpret_cast<ushort4*>(g_Ap + base + 64) = lv;
}

__global__ __launch_bounds__(256)
void splitW_kernel(const float* __restrict__ w, int z)
{
    int i = blockIdx.x * 256 + threadIdx.x;
    if (i >= DD * DD / 4) return;
    float4 v = reinterpret_cast<const float4*>(w)[i];
    int lin = i * 4;
    int n = lin >> 10;
    int k = lin & 1023;
    int chunk = k >> 5, pos = k & 31;
    ushort4 hv, lv;
    split4(v, hv, lv);
    size_t base = (size_t)(z * DD + n) * ROWB + chunk * 128 + pos * 2;
    *reinterpret_cast<ushort4*>(g_Bp + base)      = hv;
    *reinterpret_cast<ushort4*>(g_Bp + base + 64) = lv;
}

// ---------------------------------------------------------------------------
// bf16 HMMA GEMM + activation epilogue (split-precision, packed hi|lo rows)
// grid (NTOT/CTA_N = 24, MM/CTA_M = 128), 256 threads, 8 warps of 32x64
// 3-stage cp.async pipeline, 1 barrier per stage, 2 CTAs/SM
// ---------------------------------------------------------------------------
__global__ __launch_bounds__(256, 2)
void gemm_hmma_kernel(const float* __restrict__ bg,
                      const float* __restrict__ bv,
                      const float* __restrict__ bd)
{
    extern __shared__ char smem[];
    const uint32_t smb = smem_u32(smem);

    const int tid  = threadIdx.x;
    const int wid  = tid >> 5;
    const int lane = tid & 31;
    const int wm = wid & 3;          // m-tile of 32 (4 tiles)
    const int wn = wid >> 2;         // n-tile of 64 (2 tiles)

    const int bn = blockIdx.x * CTA_N;
    const int bm = blockIdx.y * CTA_M;

    const unsigned char* Ab = g_Ap + (size_t)bm * ROWB;
    const unsigned char* Bb = g_Bp + (size_t)bn * ROWB;

    float acc[2][8][4];
#pragma unroll
    for (int i = 0; i < 2; ++i)
#pragma unroll
        for (int j = 0; j < 8; ++j)
#pragma unroll
            for (int q = 0; q < 4; ++q) acc[i][j][q] = 0.0f;

    // prefetch k-chunk c into pipeline slot
    auto prefetch = [&](int c, int slot) {
        const uint32_t stA = smb + slot * STAGE_BYTES;
        const uint32_t stB = stA + OFF_B;
        // A: 128 rows x 8 chunks of 16B = 1024; 256 threads -> 4 iters
#pragma unroll
        for (int it = 0; it < 4; ++it) {
            int u = tid + it * 256;
            int row = u >> 3, blk = u & 7;
            CP_ASYNC16(stA + SWZ(row * 128 + blk * 16),
                       Ab + (size_t)row * ROWB + c * 128 + blk * 16);
        }
#pragma unroll
        for (int it = 0; it < 4; ++it) {
            int u = tid + it * 256;
            int row = u >> 3, blk = u & 7;
            CP_ASYNC16(stB + SWZ(row * 128 + blk * 16),
                       Bb + (size_t)row * ROWB + c * 128 + blk * 16);
        }
        CP_COMMIT();
    };

    prefetch(0, 0);
    prefetch(1, 1);

    for (int c = 0; c < NSTG; ++c) {
        const int slot = c % NPIPE;
        if (c == NSTG - 1) { CP_WAIT(0); } else { CP_WAIT(1); }
        __syncthreads();                      // stage c visible; slot (c+2)%3 free
        if (c + 2 < NSTG) prefetch(c + 2, (c + 2) % NPIPE);

        const uint32_t stA = smb + slot * STAGE_BYTES;
        const uint32_t stB = stA + OFF_B;

#pragma unroll
        for (int ks = 0; ks < 2; ++ks) {       // two k16 steps per k32 chunk
            // A hi/lo fragments
            uint32_t ah[2][4], al[2][4];
#pragma unroll
            for (int mi = 0; mi < 2; ++mi) {
                int rowA = wm * 32 + mi * 16 + (lane & 15);
                uint32_t base = rowA * 128 + ks * 32 + ((lane >> 4) << 4);
                LDSM_X4(ah[mi][0], ah[mi][1], ah[mi][2], ah[mi][3], stA + SWZ(base));
                LDSM_X4(al[mi][0], al[mi][1], al[mi][2], al[mi][3], stA + SWZ(base + 64));
            }
            // B hi fragments
            uint32_t bh[8][2];
#pragma unroll
            for (int p = 0; p < 4; ++p) {
                int nrow = wn * 64 + p * 16 + (lane & 7) + ((lane >> 4) << 3);
                uint32_t base = nrow * 128 + ks * 32 + (((lane >> 3) & 1) << 4);
                uint32_t r0, r1, r2, r3;
                LDSM_X4(r0, r1, r2, r3, stB + SWZ(base));
                bh[2 * p][0] = r0; bh[2 * p][1] = r1;
                bh[2 * p + 1][0] = r2; bh[2 * p + 1][1] = r3;
            }
            // products using bh: ah*bh + al*bh
#pragma unroll
            for (int mi = 0; mi < 2; ++mi)
#pragma unroll
                for (int ni = 0; ni < 8; ++ni) {
                    MMA_BF16(acc[mi][ni], ah[mi], bh[ni]);
                    MMA_BF16(acc[mi][ni], al[mi], bh[ni]);
                }
            // B lo fragments (reuse bh registers)
#pragma unroll
            for (int p = 0; p < 4; ++p) {
                int nrow = wn * 64 + p * 16 + (lane & 7) + ((lane >> 4) << 3);
                uint32_t base = nrow * 128 + ks * 32 + (((lane >> 3) & 1) << 4);
                uint32_t r0, r1, r2, r3;
                LDSM_X4(r0, r1, r2, r3, stB + SWZ(base + 64));
                bh[2 * p][0] = r0; bh[2 * p][1] = r1;
                bh[2 * p + 1][0] = r2; bh[2 * p + 1][1] = r3;
            }
            // product ah*bl
#pragma unroll
            for (int mi = 0; mi < 2; ++mi)
#pragma unroll
                for (int ni = 0; ni < 8; ++ni)
                    MMA_BF16(acc[mi][ni], ah[mi], bh[ni]);
        }
    }

    // Epilogue: bias + activation, write fp32
    const int z = blockIdx.x >> 3;          // 24 x-CTAs: 8 per output
    const int nloc = bn & 1023;
    const float* bias = (z == 0) ? bg : (z == 1) ? bv : bd;
    float* outp = (z == 0) ? g_bufG : (z == 1) ? g_bufV : g_bufA;

#pragma unroll
    for (int mi = 0; mi < 2; ++mi) {
#pragma unroll
        for (int ni = 0; ni < 8; ++ni) {
            int row0 = bm + wm * 32 + mi * 16 + (lane >> 2);
            int col  = nloc + wn * 64 + ni * 8 + (lane & 3) * 2;
            float b0 = bias[col], b1 = bias[col + 1];
#pragma unroll
            for (int half = 0; half < 2; ++half) {
                int row = row0 + half * 8;
                float v0 = acc[mi][ni][half * 2 + 0] + b0;
                float v1 = acc[mi][ni][half * 2 + 1] + b1;
                float r0, r1;
                if (z == 0) {
                    r0 = 1.0f / (1.0f + __expf(-v0));
                    r1 = 1.0f / (1.0f + __expf(-v1));
                } else if (z == 1) {
                    r0 = tanhf(v0);
                    r1 = tanhf(v1);
                } else {
                    r0 = 0.001f + 0.998f / (1.0f + __expf(-v0));
                    r1 = 0.001f + 0.998f / (1.0f + __expf(-v1));
                }
                float2 o2; o2.x = r0; o2.y = r1;
                *reinterpret_cast<float2*>(outp + (size_t)row * DD + col) = o2;
            }
        }
    }
}

// ---------------------------------------------------------------------------
// Scan passes
// ---------------------------------------------------------------------------
__global__ __launch_bounds__(256)
void scan_pass1_kernel()
{
    const int d = blockIdx.x * 256 + threadIdx.x;
    const int c = blockIdx.y;
    const int b = blockIdx.z;

    size_t base = ((size_t)(b * SS + c * LL)) * DD + d;
    float A = 1.0f;
    float h = 0.0f;
#pragma unroll 4
    for (int s = 0; s < LL; ++s) {
        float a  = g_bufA[base];
        float xg = g_bufG[base];
        float xv = g_bufV[base];
        A *= a;
        h = fmaf(a, h, xg * xv);
        base += DD;
    }
    const size_t ci = (size_t)(b * CH + c) * DD + d;
    g_cA[ci] = A;
    g_cH[ci] = h;
}

__global__ __launch_bounds__(256)
void scan_pass2_kernel()
{
    const int d = blockIdx.x * 256 + threadIdx.x;
    const int b = blockIdx.y;

    float h = 0.0f;
#pragma unroll 4
    for (int c = 0; c < CH; ++c) {
        const size_t ci = (size_t)(b * CH + c) * DD + d;
        g_hin[ci] = h;
        h = fmaf(g_cA[ci], h, g_cH[ci]);
    }
}

__global__ __launch_bounds__(256)
void scan_pass3_kernel(float* __restrict__ out)
{
    const int d = blockIdx.x * 256 + threadIdx.x;
    const int c = blockIdx.y;
    const int b = blockIdx.z;

    size_t base = ((size_t)(b * SS + c * LL)) * DD + d;
    float h = g_hin[(size_t)(b * CH + c) * DD + d];
#pragma unroll 4
    for (int s = 0; s < LL; ++s) {
        float a  = g_bufA[base];
        float xg = g_bufG[base];
        float xv = g_bufV[base];
        h = fmaf(a, h, xg * xv);
        out[base] = h;
        base += DD;
    }
}

// ---------------------------------------------------------------------------
// Launch
// ---------------------------------------------------------------------------
extern "C" void kernel_launch(void* const* d_in, const int* in_sizes, int n_in,
                              void* d_out, int out_size)
{
    const float* x  = (const float*)d_in[0];
    const float* Wg = (const float*)d_in[1];
    const float* bg = (const float*)d_in[2];
    const float* Wv = (const float*)d_in[3];
    const float* bv = (const float*)d_in[4];
    const float* Wd = (const float*)d_in[5];
    const float* bd = (const float*)d_in[6];
    float* out = (float*)d_out;

    cudaFuncSetAttribute(gemm_hmma_kernel,
                         cudaFuncAttributeMaxDynamicSharedMemorySize, SMEM_GEMM);

    splitX_kernel<<<(MM * DD / 4 + 255) / 256, 256>>>(x);
    splitW_kernel<<<(DD * DD / 4 + 255) / 256, 256>>>(Wg, 0);
    splitW_kernel<<<(DD * DD / 4 + 255) / 256, 256>>>(Wv, 1);
    splitW_kernel<<<(DD * DD / 4 + 255) / 256, 256>>>(Wd, 2);

    gemm_hmma_kernel<<<dim3(NTOT / CTA_N, MM / CTA_M), 256, SMEM_GEMM>>>(bg, bv, bd);

    dim3 p1(DD / 256, CH, BB);
    scan_pass1_kernel<<<p1, 256>>>();
    dim3 p2(DD / 256, BB);
    scan_pass2_kernel<<<p2, 256>>>();
    scan_pass3_kernel<<<p1, 256>>>(out);
}